// round 5
// baseline (speedup 1.0000x reference)
#include <cuda_runtime.h>
#include <cstdint>

// Problem constants (DiffnapsNet_42030549959310)
#define BV 4096   // batch
#define DV 8192   // data dim
#define HV 4096   // hidden
#define LV 128    // labels

// ---------------------------------------------------------------------------
// Scratch (device globals; no allocation allowed)
// ---------------------------------------------------------------------------
__device__ __align__(16) uint32_t g_x_bits[(size_t)BV * (DV / 32)];   // [B][D/32]
__device__ __align__(16) uint32_t g_w_bits[(size_t)HV * (DV / 32)];   // [H][D/32]
__device__ __align__(16) uint32_t g_wT_bits[(size_t)DV * (HV / 32)];  // [D][H/32]
__device__ __align__(16) uint32_t g_z_bits[(size_t)BV * (HV / 32)];   // [B][H/32]

// ---------------------------------------------------------------------------
// Pack a row-major float matrix into bits along the contiguous dimension.
// bit i of word w  <->  element w*32+i   (ballot: bit laneid = pred of lane)
// n must be a multiple of 256 (always true here).
// ---------------------------------------------------------------------------
__global__ void pack_bits_kernel(const float* __restrict__ src,
                                 uint32_t* __restrict__ dst, int n) {
    int i = blockIdx.x * blockDim.x + threadIdx.x;
    if (i < n) {
        unsigned m = __ballot_sync(0xffffffffu, src[i] > 0.5f);
        if ((i & 31) == 0) dst[i >> 5] = m;
    }
}

// ---------------------------------------------------------------------------
// Pack transposed: wT_bits[d][hw] bit i = (w[(hw*32+i)*D + d] > 0.5)
// Coalesced across d for each of the 32 strided rows.
// ---------------------------------------------------------------------------
__global__ void pack_transpose_kernel(const float* __restrict__ w,
                                      uint32_t* __restrict__ wT) {
    int d  = blockIdx.x * blockDim.x + threadIdx.x;  // 0..DV-1
    int hw = blockIdx.y;                             // 0..HV/32-1
    const float* col = w + (size_t)hw * 32 * DV + d;
    uint32_t word = 0;
#pragma unroll
    for (int i = 0; i < 32; i++)
        word |= (col[(size_t)i * DV] > 0.5f) ? (1u << i) : 0u;
    wT[(size_t)d * (HV / 32) + hw] = word;
}

// ---------------------------------------------------------------------------
// Binary popcount GEMM:
//   cnt[m][n] = sum_w popc(A[m][w] & B[n][w]),  then
//   C[m][n]   = ((float)cnt + bias[n] > 1.0f) ? 1.0f : 0.0f
// A: [M][KW] words, Bm: [N][KW] words, C: [M][N] floats.
// Tile 128x128, 256 threads, 8x8 per-thread register tile.
// Shared rows padded to 20 words to avoid 512B-stride bank conflicts.
// ---------------------------------------------------------------------------
template <int KW>
__global__ __launch_bounds__(256) void binpop_gemm_kernel(
    const uint32_t* __restrict__ A, const uint32_t* __restrict__ Bm,
    const float* __restrict__ bias, float* __restrict__ C, int N) {
    constexpr int BKW = 16;   // K words per stage
    constexpr int LDP = 20;   // padded shared row stride (words)
    __shared__ uint32_t As[128 * LDP];
    __shared__ uint32_t Bs[128 * LDP];

    const int tid = threadIdx.x;
    const int tx  = tid & 15;   // N direction (cols tx + 16*j)
    const int ty  = tid >> 4;   // M direction (rows ty + 16*i)
    const int m0  = blockIdx.y * 128;
    const int n0  = blockIdx.x * 128;

    // Global->shared mapping: 128 rows x 16 words; uint4 per thread, 2 passes.
    const int lr = tid >> 2;         // 0..63
    const int lq = (tid & 3) * 4;    // word offset within stage: 0,4,8,12

    const uint32_t* Ag = A + (size_t)m0 * KW;
    const uint32_t* Bg = Bm + (size_t)n0 * KW;

    int acc[8][8];
#pragma unroll
    for (int i = 0; i < 8; i++)
#pragma unroll
        for (int j = 0; j < 8; j++) acc[i][j] = 0;

    for (int kt = 0; kt < KW / BKW; kt++) {
        const int kw0 = kt * BKW;
        uint4 a0 = *(const uint4*)(Ag + (size_t)lr * KW + kw0 + lq);
        uint4 a1 = *(const uint4*)(Ag + (size_t)(lr + 64) * KW + kw0 + lq);
        uint4 b0 = *(const uint4*)(Bg + (size_t)lr * KW + kw0 + lq);
        uint4 b1 = *(const uint4*)(Bg + (size_t)(lr + 64) * KW + kw0 + lq);
        __syncthreads();  // previous stage's compute done before overwrite
        *(uint4*)&As[lr * LDP + lq]        = a0;
        *(uint4*)&As[(lr + 64) * LDP + lq] = a1;
        *(uint4*)&Bs[lr * LDP + lq]        = b0;
        *(uint4*)&Bs[(lr + 64) * LDP + lq] = b1;
        __syncthreads();

#pragma unroll
        for (int k4 = 0; k4 < 4; k4++) {
            uint4 bv[8];
#pragma unroll
            for (int j = 0; j < 8; j++)
                bv[j] = *(const uint4*)&Bs[(tx + 16 * j) * LDP + k4 * 4];
#pragma unroll
            for (int i = 0; i < 8; i++) {
                uint4 av = *(const uint4*)&As[(ty + 16 * i) * LDP + k4 * 4];
#pragma unroll
                for (int j = 0; j < 8; j++) {
                    acc[i][j] += __popc(av.x & bv[j].x) + __popc(av.y & bv[j].y) +
                                 __popc(av.z & bv[j].z) + __popc(av.w & bv[j].w);
                }
            }
        }
    }

    // Epilogue: threshold (> 1.0) with per-column bias.
#pragma unroll
    for (int i = 0; i < 8; i++) {
        const int m = m0 + ty + 16 * i;
        float* Crow = C + (size_t)m * N + n0;
#pragma unroll
        for (int j = 0; j < 8; j++) {
            const int n = tx + 16 * j;
            float v = (float)acc[i][j] + bias[n0 + n];
            Crow[n] = (v > 1.0f) ? 1.0f : 0.0f;
        }
    }
}

// ---------------------------------------------------------------------------
// Classifier GEMM (fp32): C[b][l] = sum_h Z[b][h] * W[l][h]
// M=BV, N=LV=128 (full width per block), K=HV. 32-row block tile, 128 blocks.
// K-major shared tiles so operand loads are float4 (2 LDS.128 per 16 FFMA).
// ---------------------------------------------------------------------------
__global__ __launch_bounds__(256) void clf_gemm_kernel(
    const float* __restrict__ Z,   // [BV][HV]
    const float* __restrict__ W,   // [LV][HV]
    float* __restrict__ C) {       // [BV][LV]
    constexpr int BK = 32;
    __shared__ float Zs[BK][36];    // [k][m], padded (36*4 % 16 == 0)
    __shared__ float Ws[BK][132];   // [k][l], padded (132*4 % 16 == 0)

    const int tid  = threadIdx.x;
    const int lane = tid & 31;   // cols lane*4 + c
    const int wid  = tid >> 5;   // rows wid*4 + i
    const int m0   = blockIdx.x * 32;

    float acc[4][4];
#pragma unroll
    for (int i = 0; i < 4; i++)
#pragma unroll
        for (int c = 0; c < 4; c++) acc[i][c] = 0.0f;

    for (int kt = 0; kt < HV / BK; kt++) {
        const int k0 = kt * BK;
        __syncthreads();
        // Fill Zs: 32x32 elements (coalesced in k)
#pragma unroll
        for (int p = 0; p < 4; p++) {
            int e = tid + p * 256;
            int m = e >> 5, k = e & 31;
            Zs[k][m] = Z[(size_t)(m0 + m) * HV + k0 + k];
        }
        // Fill Ws: 128x32 elements (coalesced in k)
#pragma unroll
        for (int p = 0; p < 16; p++) {
            int e = tid + p * 256;
            int l = e >> 5, k = e & 31;
            Ws[k][l] = W[(size_t)l * HV + k0 + k];
        }
        __syncthreads();

#pragma unroll
        for (int k = 0; k < BK; k++) {
            float4 z4 = *(const float4*)&Zs[k][wid * 4];
            float4 w4 = *(const float4*)&Ws[k][lane * 4];
            acc[0][0] += z4.x * w4.x; acc[0][1] += z4.x * w4.y;
            acc[0][2] += z4.x * w4.z; acc[0][3] += z4.x * w4.w;
            acc[1][0] += z4.y * w4.x; acc[1][1] += z4.y * w4.y;
            acc[1][2] += z4.y * w4.z; acc[1][3] += z4.y * w4.w;
            acc[2][0] += z4.z * w4.x; acc[2][1] += z4.z * w4.y;
            acc[2][2] += z4.z * w4.z; acc[2][3] += z4.z * w4.w;
            acc[3][0] += z4.w * w4.x; acc[3][1] += z4.w * w4.y;
            acc[3][2] += z4.w * w4.z; acc[3][3] += z4.w * w4.w;
        }
    }

#pragma unroll
    for (int i = 0; i < 4; i++) {
        int row = m0 + wid * 4 + i;
        float4 v = make_float4(acc[i][0], acc[i][1], acc[i][2], acc[i][3]);
        *(float4*)&C[(size_t)row * LV + lane * 4] = v;
    }
}

// ---------------------------------------------------------------------------
// Launch: pack -> GEMM1 (z) -> pack z -> GEMM2 (output) -> classifier
// Output layout: [output (B*D) | classification (B*L) | z (B*H)], float32.
// ---------------------------------------------------------------------------
extern "C" void kernel_launch(void* const* d_in, const int* in_sizes, int n_in,
                              void* d_out, int out_size) {
    const float* x     = (const float*)d_in[0];  // [B,D]
    const float* w     = (const float*)d_in[1];  // [H,D]
    const float* bias0 = (const float*)d_in[2];  // [H]
    const float* bias3 = (const float*)d_in[3];  // [D]
    const float* clf   = (const float*)d_in[4];  // [L,H]

    float* out        = (float*)d_out;
    float* out_output = out;                                        // B*D
    float* out_class  = out + (size_t)BV * DV;                      // B*L
    float* out_z      = out + (size_t)BV * DV + (size_t)BV * LV;    // B*H

    uint32_t *xb = nullptr, *wb = nullptr, *wtb = nullptr, *zb = nullptr;
    cudaGetSymbolAddress((void**)&xb, g_x_bits);
    cudaGetSymbolAddress((void**)&wb, g_w_bits);
    cudaGetSymbolAddress((void**)&wtb, g_wT_bits);
    cudaGetSymbolAddress((void**)&zb, g_z_bits);

    // 1) Pack x -> x_bits   (B*D elements)
    pack_bits_kernel<<<(BV * DV) / 256, 256>>>(x, xb, BV * DV);
    // 2) Pack enc_weight -> w_bits (H*D elements)
    pack_bits_kernel<<<(HV * DV) / 256, 256>>>(w, wb, HV * DV);
    // 3) Pack transposed enc_weight -> wT_bits
    pack_transpose_kernel<<<dim3(DV / 256, HV / 32), 256>>>(w, wtb);
    // 4) GEMM1: h = x @ wb^T ; z = (h + bias0 > 1)
    binpop_gemm_kernel<DV / 32>
        <<<dim3(HV / 128, BV / 128), 256>>>(xb, wb, bias0, out_z, HV);
    // 5) Pack z -> z_bits
    pack_bits_kernel<<<(BV * HV) / 256, 256>>>(out_z, zb, BV * HV);
    // 6) GEMM2: recon = z @ wb ; output = (recon + bias3 > 1)
    binpop_gemm_kernel<HV / 32>
        <<<dim3(DV / 128, BV / 128), 256>>>(zb, wtb, bias3, out_output, DV);
    // 7) classification = z @ clf^T
    clf_gemm_kernel<<<BV / 32, 256>>>(out_z, clf, out_class);
}

// round 7
// speedup vs baseline: 1.1075x; 1.1075x over previous
#include <cuda_runtime.h>
#include <cstdint>

// Problem constants (DiffnapsNet_42030549959310)
#define BV 4096   // batch
#define DV 8192   // data dim
#define HV 4096   // hidden
#define LV 128    // labels

#define FP8_ONE 0x38u   // e4m3 encoding of 1.0f

// ---------------------------------------------------------------------------
// Scratch (device globals; no allocation allowed) — fp8 (e4m3) operands
// ---------------------------------------------------------------------------
__device__ __align__(16) uint8_t g_x8[(size_t)BV * DV];   // [B][D]
__device__ __align__(16) uint8_t g_w8[(size_t)HV * DV];   // [H][D]
__device__ __align__(16) uint8_t g_wT8[(size_t)DV * HV];  // [D][H]
__device__ __align__(16) uint8_t g_z8[(size_t)BV * HV];   // [B][H]

// ---------------------------------------------------------------------------
// PTX helpers (all family-compatible: sm_80/89+ features, no tcgen05)
// ---------------------------------------------------------------------------
__device__ __forceinline__ uint32_t smem_u32(const void* p) {
    uint32_t a;
    asm("{ .reg .u64 t; cvta.to.shared.u64 t, %1; cvt.u32.u64 %0, t; }"
        : "=r"(a) : "l"(p));
    return a;
}

__device__ __forceinline__ void cp16(uint32_t dst, const void* src) {
    asm volatile("cp.async.cg.shared.global [%0], [%1], 16;"
                 :: "r"(dst), "l"(src) : "memory");
}
#define CP_COMMIT() asm volatile("cp.async.commit_group;" ::: "memory")
#define CP_WAIT(n)  asm volatile("cp.async.wait_group %0;" :: "n"(n) : "memory")

__device__ __forceinline__ void ldm_x4(uint32_t (&r)[4], uint32_t addr) {
    asm volatile("ldmatrix.sync.aligned.m8n8.x4.shared.b16 {%0,%1,%2,%3}, [%4];"
                 : "=r"(r[0]), "=r"(r[1]), "=r"(r[2]), "=r"(r[3]) : "r"(addr));
}

__device__ __forceinline__ void mma_fp8(float (&c)[4], const uint32_t (&a)[4],
                                        uint32_t b0, uint32_t b1) {
    asm volatile(
        "mma.sync.aligned.m16n8k32.row.col.f32.e4m3.e4m3.f32 "
        "{%0,%1,%2,%3}, {%4,%5,%6,%7}, {%8,%9}, {%0,%1,%2,%3};"
        : "+f"(c[0]), "+f"(c[1]), "+f"(c[2]), "+f"(c[3])
        : "r"(a[0]), "r"(a[1]), "r"(a[2]), "r"(a[3]), "r"(b0), "r"(b1));
}

// ---------------------------------------------------------------------------
// Conversion: float {0,1} -> e4m3 byte {0x00, 0x38}
// ---------------------------------------------------------------------------
__global__ void cvt_fp8_kernel(const float* __restrict__ src,
                               uint32_t* __restrict__ dst, int n4) {
    int i = blockIdx.x * blockDim.x + threadIdx.x;
    if (i < n4) {
        float4 v = ((const float4*)src)[i];
        uint32_t w = (v.x > 0.5f ? FP8_ONE : 0u) | (v.y > 0.5f ? FP8_ONE << 8 : 0u) |
                     (v.z > 0.5f ? FP8_ONE << 16 : 0u) | (v.w > 0.5f ? FP8_ONE << 24 : 0u);
        dst[i] = w;
    }
}

// Transposed conversion: wT8[d][h] = (w[h][d] > 0.5) ? 1.0e4m3 : 0
__global__ void cvt_fp8_transpose_kernel(const float* __restrict__ w,
                                         uint8_t* __restrict__ wT) {
    int d  = blockIdx.x * blockDim.x + threadIdx.x;  // 0..DV-1
    int hw = blockIdx.y;                             // 0..HV/32-1
    const float* col = w + (size_t)hw * 32 * DV + d;
    uint32_t wd[8];
#pragma unroll
    for (int q = 0; q < 8; q++) {
        uint32_t v = 0;
#pragma unroll
        for (int c = 0; c < 4; c++)
            if (col[(size_t)(q * 4 + c) * DV] > 0.5f) v |= FP8_ONE << (c * 8);
        wd[q] = v;
    }
    uint4* dst = (uint4*)(wT + (size_t)d * HV + hw * 32);
    dst[0] = make_uint4(wd[0], wd[1], wd[2], wd[3]);
    dst[1] = make_uint4(wd[4], wd[5], wd[6], wd[7]);
}

// ---------------------------------------------------------------------------
// FP8 mma.sync GEMM with thresholded epilogue.
//   cnt[m][n] = sum_k A[m][k]*B[n][k]   (exact integer counts in fp32)
//   Cf[m][n]  = (cnt + bias[n] > 1) ? 1 : 0;  optionally packed e4m3 C8.
// CTA tile 128(M)x128(N), 8 warps in 4x2 grid, warp tile 32x64.
// K-chunks of 64 bytes, cp.async double-buffered smem, 80B row stride
// (20-word stride -> banks {0,20,8,28,16,4,24,12}: ldmatrix conflict-free).
// ---------------------------------------------------------------------------
#define LDT 80          // smem row stride in bytes
#define TILE_BYTES (128 * LDT)  // 10240

template <int KB, bool WRITE_FP8>
__global__ __launch_bounds__(256, 1) void fp8_mma_gemm_kernel(
    const uint8_t* __restrict__ A, const uint8_t* __restrict__ Bm,
    const float* __restrict__ bias, float* __restrict__ Cf,
    uint8_t* __restrict__ C8, int Ntot) {
    constexpr int NCH = KB / 64;
    __shared__ __align__(16) uint8_t sm_tiles[2][2][TILE_BYTES];  // [buf][A=0/B=1]

    const int tid  = threadIdx.x;
    const int lane = tid & 31;
    const int wid  = tid >> 5;
    const int wm   = wid & 3;   // 0..3 -> m offset wm*32
    const int wn   = wid >> 2;  // 0..1 -> n offset wn*64
    const int m0   = blockIdx.y * 128;
    const int n0   = blockIdx.x * 128;

    const uint8_t* Ag = A + (size_t)m0 * KB;
    const uint8_t* Bg = Bm + (size_t)n0 * KB;

    // global->smem mapping (per thread: 2 A rows-chunks + 2 B)
    const int gr = tid >> 2;        // row / 2-pass
    const int gq = (tid & 3) * 16;  // 16B chunk within 64B row

    const uint32_t sa[2] = {smem_u32(sm_tiles[0][0]), smem_u32(sm_tiles[1][0])};
    const uint32_t sb[2] = {smem_u32(sm_tiles[0][1]), smem_u32(sm_tiles[1][1])};

    // ldmatrix per-lane address offsets (byte offsets into a tile)
    // A (x4): lane i -> row (i&7) + ((i>>3)&1)*8, 16B chunk qc = ks*2 + (i>>4)
    const int a_row = wm * 32 + (lane & 7) + ((lane >> 3) & 1) * 8;
    const int a_qc  = (lane >> 4);              // + ks*2
    // B (x4, nt pair): lane i -> ntile +(i>>4), row (i&7), qc = ks*2 + ((i>>3)&1)
    const int b_rowbase = wn * 64 + (lane & 7); // + (2*nt2 + (lane>>4))*8
    const int b_nt      = ((lane >> 4) & 1);
    const int b_qc      = ((lane >> 3) & 1);    // + ks*2

    float acc[2][8][4];
#pragma unroll
    for (int mt = 0; mt < 2; mt++)
#pragma unroll
        for (int nt = 0; nt < 8; nt++)
#pragma unroll
            for (int c = 0; c < 4; c++) acc[mt][nt][c] = 0.0f;

    // --- prologue: load chunk 0 into buf 0 ---
    {
        const int kc = 0;
#pragma unroll
        for (int p = 0; p < 2; p++) {
            int r = gr + p * 64;
            cp16(sa[0] + r * LDT + gq, Ag + (size_t)r * KB + kc + gq);
            cp16(sb[0] + r * LDT + gq, Bg + (size_t)r * KB + kc + gq);
        }
        CP_COMMIT();
    }

    for (int ch = 0; ch < NCH; ch++) {
        const int buf = ch & 1;
        if (ch + 1 < NCH) {
            const int kc = (ch + 1) * 64, nb = buf ^ 1;
#pragma unroll
            for (int p = 0; p < 2; p++) {
                int r = gr + p * 64;
                cp16(sa[nb] + r * LDT + gq, Ag + (size_t)r * KB + kc + gq);
                cp16(sb[nb] + r * LDT + gq, Bg + (size_t)r * KB + kc + gq);
            }
            CP_COMMIT();
            CP_WAIT(1);
        } else {
            CP_WAIT(0);
        }
        __syncthreads();

#pragma unroll
        for (int ks = 0; ks < 2; ks++) {
            uint32_t af[2][4];
#pragma unroll
            for (int mt = 0; mt < 2; mt++)
                ldm_x4(af[mt], sa[buf] + (a_row + mt * 16) * LDT +
                                   (ks * 2 + a_qc) * 16);
            uint32_t bf[8][2];
#pragma unroll
            for (int nt2 = 0; nt2 < 4; nt2++) {
                uint32_t t[4];
                ldm_x4(t, sb[buf] + (b_rowbase + (2 * nt2 + b_nt) * 8) * LDT +
                              (ks * 2 + b_qc) * 16);
                bf[2 * nt2][0] = t[0]; bf[2 * nt2][1] = t[1];
                bf[2 * nt2 + 1][0] = t[2]; bf[2 * nt2 + 1][1] = t[3];
            }
#pragma unroll
            for (int mt = 0; mt < 2; mt++)
#pragma unroll
                for (int nt = 0; nt < 8; nt++)
                    mma_fp8(acc[mt][nt], af[mt], bf[nt][0], bf[nt][1]);
        }
        __syncthreads();
    }

    // --- epilogue: threshold with per-column bias; write float (+fp8) ---
    {
        const int g  = lane >> 2;
        const int tg = lane & 3;
        const int rbase = m0 + wm * 32 + g;
        const int cbase = n0 + wn * 64 + tg * 2;
        float2 bp[8];
#pragma unroll
        for (int nt = 0; nt < 8; nt++) {
            bp[nt].x = bias[cbase + nt * 8];
            bp[nt].y = bias[cbase + nt * 8 + 1];
        }
#pragma unroll
        for (int mt = 0; mt < 2; mt++) {
            const int r0 = rbase + mt * 16;
            const int r1 = r0 + 8;
#pragma unroll
            for (int nt = 0; nt < 8; nt++) {
                const int c = cbase + nt * 8;
                float v00 = (acc[mt][nt][0] + bp[nt].x > 1.0f) ? 1.0f : 0.0f;
                float v01 = (acc[mt][nt][1] + bp[nt].y > 1.0f) ? 1.0f : 0.0f;
                float v10 = (acc[mt][nt][2] + bp[nt].x > 1.0f) ? 1.0f : 0.0f;
                float v11 = (acc[mt][nt][3] + bp[nt].y > 1.0f) ? 1.0f : 0.0f;
                *(float2*)(Cf + (size_t)r0 * Ntot + c) = make_float2(v00, v01);
                *(float2*)(Cf + (size_t)r1 * Ntot + c) = make_float2(v10, v11);
                if (WRITE_FP8) {
                    uint16_t p0 = (uint16_t)((v00 != 0.0f ? FP8_ONE : 0u) |
                                             (v01 != 0.0f ? FP8_ONE << 8 : 0u));
                    uint16_t p1 = (uint16_t)((v10 != 0.0f ? FP8_ONE : 0u) |
                                             (v11 != 0.0f ? FP8_ONE << 8 : 0u));
                    *(uint16_t*)(C8 + (size_t)r0 * Ntot + c) = p0;
                    *(uint16_t*)(C8 + (size_t)r1 * Ntot + c) = p1;
                }
            }
        }
    }
}

// ---------------------------------------------------------------------------
// Classifier GEMM (fp32): C[b][l] = sum_h Z[b][h] * W[l][h]
// ---------------------------------------------------------------------------
__global__ __launch_bounds__(256) void clf_gemm_kernel(
    const float* __restrict__ Z, const float* __restrict__ W,
    float* __restrict__ C) {
    constexpr int BK = 32;
    __shared__ float Zs[BK][36];
    __shared__ float Ws[BK][132];

    const int tid  = threadIdx.x;
    const int lane = tid & 31;
    const int wid  = tid >> 5;
    const int m0   = blockIdx.x * 32;

    float acc[4][4];
#pragma unroll
    for (int i = 0; i < 4; i++)
#pragma unroll
        for (int c = 0; c < 4; c++) acc[i][c] = 0.0f;

    for (int kt = 0; kt < HV / BK; kt++) {
        const int k0 = kt * BK;
        __syncthreads();
#pragma unroll
        for (int p = 0; p < 4; p++) {
            int e = tid + p * 256;
            int m = e >> 5, k = e & 31;
            Zs[k][m] = Z[(size_t)(m0 + m) * HV + k0 + k];
        }
#pragma unroll
        for (int p = 0; p < 16; p++) {
            int e = tid + p * 256;
            int l = e >> 5, k = e & 31;
            Ws[k][l] = W[(size_t)l * HV + k0 + k];
        }
        __syncthreads();

#pragma unroll
        for (int k = 0; k < BK; k++) {
            float4 z4 = *(const float4*)&Zs[k][wid * 4];
            float4 w4 = *(const float4*)&Ws[k][lane * 4];
            acc[0][0] += z4.x * w4.x; acc[0][1] += z4.x * w4.y;
            acc[0][2] += z4.x * w4.z; acc[0][3] += z4.x * w4.w;
            acc[1][0] += z4.y * w4.x; acc[1][1] += z4.y * w4.y;
            acc[1][2] += z4.y * w4.z; acc[1][3] += z4.y * w4.w;
            acc[2][0] += z4.z * w4.x; acc[2][1] += z4.z * w4.y;
            acc[2][2] += z4.z * w4.z; acc[2][3] += z4.z * w4.w;
            acc[3][0] += z4.w * w4.x; acc[3][1] += z4.w * w4.y;
            acc[3][2] += z4.w * w4.z; acc[3][3] += z4.w * w4.w;
        }
    }

#pragma unroll
    for (int i = 0; i < 4; i++) {
        int row = m0 + wid * 4 + i;
        *(float4*)&C[(size_t)row * LV + lane * 4] =
            make_float4(acc[i][0], acc[i][1], acc[i][2], acc[i][3]);
    }
}

// ---------------------------------------------------------------------------
// Launch
// Output layout: [output (B*D) | classification (B*L) | z (B*H)], float32.
// ---------------------------------------------------------------------------
extern "C" void kernel_launch(void* const* d_in, const int* in_sizes, int n_in,
                              void* d_out, int out_size) {
    const float* x     = (const float*)d_in[0];  // [B,D]
    const float* w     = (const float*)d_in[1];  // [H,D]
    const float* bias0 = (const float*)d_in[2];  // [H]
    const float* bias3 = (const float*)d_in[3];  // [D]
    const float* clf   = (const float*)d_in[4];  // [L,H]

    float* out        = (float*)d_out;
    float* out_output = out;
    float* out_class  = out + (size_t)BV * DV;
    float* out_z      = out + (size_t)BV * DV + (size_t)BV * LV;

    uint8_t *x8, *w8, *wT8, *z8;
    cudaGetSymbolAddress((void**)&x8, g_x8);
    cudaGetSymbolAddress((void**)&w8, g_w8);
    cudaGetSymbolAddress((void**)&wT8, g_wT8);
    cudaGetSymbolAddress((void**)&z8, g_z8);

    // 1) conversions to e4m3 {0,1}
    cvt_fp8_kernel<<<(BV * DV / 4) / 256, 256>>>(x, (uint32_t*)x8, BV * DV / 4);
    cvt_fp8_kernel<<<(HV * DV / 4) / 256, 256>>>(w, (uint32_t*)w8, HV * DV / 4);
    cvt_fp8_transpose_kernel<<<dim3(DV / 256, HV / 32), 256>>>(w, wT8);

    // 2) GEMM1: h = x @ wb^T ; z = (h + bias0 > 1); also writes z in e4m3
    fp8_mma_gemm_kernel<DV, true>
        <<<dim3(HV / 128, BV / 128), 256>>>(x8, w8, bias0, out_z, z8, HV);

    // 3) GEMM2: recon = z @ wb ; output = (recon + bias3 > 1)
    fp8_mma_gemm_kernel<HV, false>
        <<<dim3(DV / 128, BV / 128), 256>>>(z8, wT8, bias3, out_output, nullptr, DV);

    // 4) classification = z @ clf^T
    clf_gemm_kernel<<<BV / 32, 256>>>(out_z, clf, out_class);
}

// round 8
// speedup vs baseline: 1.3736x; 1.2403x over previous
#include <cuda_runtime.h>
#include <cuda_bf16.h>
#include <cstdint>

// Problem constants (DiffnapsNet_42030549959310)
#define BV 4096   // batch
#define DV 8192   // data dim
#define HV 4096   // hidden
#define LV 128    // labels

#define FP8_ONE 0x38u     // e4m3 1.0
#define BF16_ONE 0x3F80u  // bf16 1.0

// ---------------------------------------------------------------------------
// Scratch (device globals; no allocation allowed)
// ---------------------------------------------------------------------------
__device__ __align__(16) uint8_t  g_x8[(size_t)BV * DV];    // [B][D] e4m3
__device__ __align__(16) uint8_t  g_w8[(size_t)HV * DV];    // [H][D] e4m3
__device__ __align__(16) uint8_t  g_wT8[(size_t)DV * HV];   // [D][H] e4m3
__device__ __align__(16) uint8_t  g_z8[(size_t)BV * HV];    // [B][H] e4m3
__device__ __align__(16) uint16_t g_zbf[(size_t)BV * HV];   // [B][H] bf16
__device__ __align__(16) uint16_t g_whi[(size_t)LV * HV];   // [L][H] bf16 hi
__device__ __align__(16) uint16_t g_wlo[(size_t)LV * HV];   // [L][H] bf16 lo

// ---------------------------------------------------------------------------
// PTX helpers (family-compatible: sm_80/89 features only)
// ---------------------------------------------------------------------------
__device__ __forceinline__ uint32_t smem_u32(const void* p) {
    uint32_t a;
    asm("{ .reg .u64 t; cvta.to.shared.u64 t, %1; cvt.u32.u64 %0, t; }"
        : "=r"(a) : "l"(p));
    return a;
}
__device__ __forceinline__ void cp16(uint32_t dst, const void* src) {
    asm volatile("cp.async.cg.shared.global [%0], [%1], 16;"
                 :: "r"(dst), "l"(src) : "memory");
}
#define CP_COMMIT() asm volatile("cp.async.commit_group;" ::: "memory")
#define CP_WAIT(n)  asm volatile("cp.async.wait_group %0;" :: "n"(n) : "memory")

__device__ __forceinline__ void ldm_x4(uint32_t (&r)[4], uint32_t addr) {
    asm volatile("ldmatrix.sync.aligned.m8n8.x4.shared.b16 {%0,%1,%2,%3}, [%4];"
                 : "=r"(r[0]), "=r"(r[1]), "=r"(r[2]), "=r"(r[3]) : "r"(addr));
}
__device__ __forceinline__ void mma_fp8(float (&c)[4], const uint32_t (&a)[4],
                                        uint32_t b0, uint32_t b1) {
    asm volatile(
        "mma.sync.aligned.m16n8k32.row.col.f32.e4m3.e4m3.f32 "
        "{%0,%1,%2,%3}, {%4,%5,%6,%7}, {%8,%9}, {%0,%1,%2,%3};"
        : "+f"(c[0]), "+f"(c[1]), "+f"(c[2]), "+f"(c[3])
        : "r"(a[0]), "r"(a[1]), "r"(a[2]), "r"(a[3]), "r"(b0), "r"(b1));
}
__device__ __forceinline__ void mma_bf16(float (&c)[4], const uint32_t (&a)[4],
                                         uint32_t b0, uint32_t b1) {
    asm volatile(
        "mma.sync.aligned.m16n8k16.row.col.f32.bf16.bf16.f32 "
        "{%0,%1,%2,%3}, {%4,%5,%6,%7}, {%8,%9}, {%0,%1,%2,%3};"
        : "+f"(c[0]), "+f"(c[1]), "+f"(c[2]), "+f"(c[3])
        : "r"(a[0]), "r"(a[1]), "r"(a[2]), "r"(a[3]), "r"(b0), "r"(b1));
}

// ---------------------------------------------------------------------------
// Conversions
// ---------------------------------------------------------------------------
__global__ void cvt_fp8_kernel(const float* __restrict__ src,
                               uint32_t* __restrict__ dst, int n4) {
    int i = blockIdx.x * blockDim.x + threadIdx.x;
    if (i < n4) {
        float4 v = ((const float4*)src)[i];
        uint32_t w = (v.x > 0.5f ? FP8_ONE : 0u) | (v.y > 0.5f ? FP8_ONE << 8 : 0u) |
                     (v.z > 0.5f ? FP8_ONE << 16 : 0u) | (v.w > 0.5f ? FP8_ONE << 24 : 0u);
        dst[i] = w;
    }
}

__global__ void cvt_fp8_transpose_kernel(const float* __restrict__ w,
                                         uint8_t* __restrict__ wT) {
    int d  = blockIdx.x * blockDim.x + threadIdx.x;
    int hw = blockIdx.y;
    const float* col = w + (size_t)hw * 32 * DV + d;
    uint32_t wd[8];
#pragma unroll
    for (int q = 0; q < 8; q++) {
        uint32_t v = 0;
#pragma unroll
        for (int c = 0; c < 4; c++)
            if (col[(size_t)(q * 4 + c) * DV] > 0.5f) v |= FP8_ONE << (c * 8);
        wd[q] = v;
    }
    uint4* dst = (uint4*)(wT + (size_t)d * HV + hw * 32);
    dst[0] = make_uint4(wd[0], wd[1], wd[2], wd[3]);
    dst[1] = make_uint4(wd[4], wd[5], wd[6], wd[7]);
}

// Exact bf16 split of classifier weights: w = hi + lo (lo residual ~2^-9 |w|)
__global__ void cvt_wsplit_kernel(const float* __restrict__ w,
                                  uint16_t* __restrict__ whi,
                                  uint16_t* __restrict__ wlo, int n) {
    int i = blockIdx.x * blockDim.x + threadIdx.x;
    if (i < n) {
        float v = w[i];
        __nv_bfloat16 h = __float2bfloat16(v);
        float r = v - __bfloat162float(h);
        __nv_bfloat16 l = __float2bfloat16(r);
        whi[i] = *(uint16_t*)&h;
        wlo[i] = *(uint16_t*)&l;
    }
}

// ---------------------------------------------------------------------------
// FP8 mma.sync GEMM, 3-stage cp.async ring, 2 CTAs/SM.
//   cnt[m][n] = sum_k A[m][k]*B[n][k]  (exact counts, fp32 accum)
//   Cf = (cnt + bias[n] > 1) ? 1 : 0;  optionally also e4m3 + bf16 copies.
// CTA 128x128, 8 warps (4x2), warp tile 32x64, K-chunks of 64B.
// Smem row stride 80B -> ldmatrix conflict-free without swizzle.
// ---------------------------------------------------------------------------
#define LDT 80
#define ATILE (128 * LDT)         // 10240
#define STAGE_B (2 * ATILE)       // 20480 (A then B)
#define GEMM_SMEM (3 * STAGE_B)   // 61440

template <int KB, bool WRITE_AUX>
__global__ __launch_bounds__(256, 2) void fp8_mma_gemm_kernel(
    const uint8_t* __restrict__ A, const uint8_t* __restrict__ Bm,
    const float* __restrict__ bias, float* __restrict__ Cf,
    uint8_t* __restrict__ C8, uint16_t* __restrict__ Cbf, int Ntot) {
    constexpr int NCH = KB / 64;
    extern __shared__ __align__(16) uint8_t smem[];
    const uint32_t s0 = smem_u32(smem);

    const int tid  = threadIdx.x;
    const int lane = tid & 31;
    const int wid  = tid >> 5;
    const int wm   = wid & 3;
    const int wn   = wid >> 2;
    const int m0   = blockIdx.y * 128;
    const int n0   = blockIdx.x * 128;

    // global->smem cp.async mapping
    const int gr = tid >> 2;
    const int gq = (tid & 3) * 16;
    const uint8_t* gA = A + (size_t)(m0 + gr) * KB + gq;
    const uint8_t* gB = Bm + (size_t)(n0 + gr) * KB + gq;
    const uint32_t wA = s0 + gr * LDT + gq;
    const uint32_t wB = wA + ATILE;

    // ldmatrix read addresses (verified layout from R7)
    const int a_row = wm * 32 + (lane & 7) + ((lane >> 3) & 1) * 8;
    const int a_qc  = (lane >> 4);
    const int b_row = wn * 64 + (lane & 7) + ((lane >> 4) & 1) * 8;
    const int b_qc  = (lane >> 3) & 1;
    const uint32_t rdA0 = s0 + a_row * LDT + a_qc * 16;
    const uint32_t rdB0 = s0 + ATILE + b_row * LDT + b_qc * 16;

    float acc[2][8][4];
#pragma unroll
    for (int mt = 0; mt < 2; mt++)
#pragma unroll
        for (int nt = 0; nt < 8; nt++)
#pragma unroll
            for (int c = 0; c < 4; c++) acc[mt][nt][c] = 0.0f;

    auto issue = [&](int ch, int st) {
        const uint32_t da = wA + st * STAGE_B;
        const uint32_t db = wB + st * STAGE_B;
        const uint8_t* pa = gA + ch * 64;
        const uint8_t* pb = gB + ch * 64;
        cp16(da, pa);
        cp16(da + 64 * LDT, pa + (size_t)64 * KB);
        cp16(db, pb);
        cp16(db + 64 * LDT, pb + (size_t)64 * KB);
        CP_COMMIT();
    };
    issue(0, 0);
    issue(1, 1);

    int st = 0, st_wr = 2;
    for (int ch = 0; ch < NCH; ch++) {
        if (ch + 1 < NCH) { CP_WAIT(1); } else { CP_WAIT(0); }
        __syncthreads();  // chunk ch visible to all; stage (ch+2)%3 free
        if (ch + 2 < NCH) {
            issue(ch + 2, st_wr);
            st_wr = (st_wr == 2) ? 0 : st_wr + 1;
        }
        const uint32_t rdA = rdA0 + st * STAGE_B;
        const uint32_t rdB = rdB0 + st * STAGE_B;
#pragma unroll
        for (int ks = 0; ks < 2; ks++) {
            uint32_t af[2][4];
            ldm_x4(af[0], rdA + ks * 32);
            ldm_x4(af[1], rdA + 16 * LDT + ks * 32);
            uint32_t bf[8][2];
#pragma unroll
            for (int nt2 = 0; nt2 < 4; nt2++) {
                uint32_t t[4];
                ldm_x4(t, rdB + nt2 * 16 * LDT + ks * 32);
                bf[2 * nt2][0] = t[0]; bf[2 * nt2][1] = t[1];
                bf[2 * nt2 + 1][0] = t[2]; bf[2 * nt2 + 1][1] = t[3];
            }
#pragma unroll
            for (int mt = 0; mt < 2; mt++)
#pragma unroll
                for (int nt = 0; nt < 8; nt++)
                    mma_fp8(acc[mt][nt], af[mt], bf[nt][0], bf[nt][1]);
        }
        st = (st == 2) ? 0 : st + 1;
    }

    // epilogue: threshold with per-column bias
    {
        const int g  = lane >> 2;
        const int tg = lane & 3;
        const int rbase = m0 + wm * 32 + g;
        const int cbase = n0 + wn * 64 + tg * 2;
#pragma unroll
        for (int mt = 0; mt < 2; mt++) {
            const int r0 = rbase + mt * 16;
            const int r1 = r0 + 8;
#pragma unroll
            for (int nt = 0; nt < 8; nt++) {
                const int c = cbase + nt * 8;
                const float bx = bias[c], by = bias[c + 1];
                float v00 = (acc[mt][nt][0] + bx > 1.0f) ? 1.0f : 0.0f;
                float v01 = (acc[mt][nt][1] + by > 1.0f) ? 1.0f : 0.0f;
                float v10 = (acc[mt][nt][2] + bx > 1.0f) ? 1.0f : 0.0f;
                float v11 = (acc[mt][nt][3] + by > 1.0f) ? 1.0f : 0.0f;
                *(float2*)(Cf + (size_t)r0 * Ntot + c) = make_float2(v00, v01);
                *(float2*)(Cf + (size_t)r1 * Ntot + c) = make_float2(v10, v11);
                if (WRITE_AUX) {
                    *(uint16_t*)(C8 + (size_t)r0 * Ntot + c) =
                        (uint16_t)((v00 != 0.0f ? FP8_ONE : 0u) |
                                   (v01 != 0.0f ? FP8_ONE << 8 : 0u));
                    *(uint16_t*)(C8 + (size_t)r1 * Ntot + c) =
                        (uint16_t)((v10 != 0.0f ? FP8_ONE : 0u) |
                                   (v11 != 0.0f ? FP8_ONE << 8 : 0u));
                    *(uint32_t*)(Cbf + (size_t)r0 * Ntot + c) =
                        (v00 != 0.0f ? BF16_ONE : 0u) |
                        (v01 != 0.0f ? BF16_ONE << 16 : 0u);
                    *(uint32_t*)(Cbf + (size_t)r1 * Ntot + c) =
                        (v10 != 0.0f ? BF16_ONE : 0u) |
                        (v11 != 0.0f ? BF16_ONE << 16 : 0u);
                }
            }
        }
    }
}

// ---------------------------------------------------------------------------
// Classifier via bf16 mma with exact W split:
//   C[b][l] = sum_h zbf[b][h] * (Whi[l][h] + Wlo[l][h])
// CTA 128(M) x 128(N = all L), 8 warps (4x2), warp tile 32x64, K-chunk 32 bf16.
// ---------------------------------------------------------------------------
#define CLF_T (128 * LDT)          // 10240 per tile
#define CLF_STG (3 * CLF_T)        // 30720 per stage (A, Whi, Wlo)
#define CLF_SMEM (3 * CLF_STG)     // 92160

__global__ __launch_bounds__(256) void clf_mma_kernel(
    const uint16_t* __restrict__ Z, const uint16_t* __restrict__ Whi,
    const uint16_t* __restrict__ Wlo, float* __restrict__ C) {
    constexpr int NCH = HV / 32;   // 64B chunks of bf16 K
    extern __shared__ __align__(16) uint8_t smem[];
    const uint32_t s0 = smem_u32(smem);

    const int tid  = threadIdx.x;
    const int lane = tid & 31;
    const int wid  = tid >> 5;
    const int wm   = wid & 3;
    const int wn   = wid >> 2;
    const int m0   = blockIdx.x * 128;

    const int gr = tid >> 2;
    const int gq = (tid & 3) * 16;
    const uint8_t* gA = (const uint8_t*)Z + ((size_t)(m0 + gr) * HV) * 2 + gq;
    const uint8_t* gH = (const uint8_t*)Whi + ((size_t)gr * HV) * 2 + gq;
    const uint8_t* gL = (const uint8_t*)Wlo + ((size_t)gr * HV) * 2 + gq;
    const uint32_t wA = s0 + gr * LDT + gq;
    const uint32_t wH = wA + CLF_T;
    const uint32_t wL = wH + CLF_T;

    const int a_row = wm * 32 + (lane & 7) + ((lane >> 3) & 1) * 8;
    const int a_qc  = (lane >> 4);
    const int b_row = wn * 64 + (lane & 7) + ((lane >> 4) & 1) * 8;
    const int b_qc  = (lane >> 3) & 1;
    const uint32_t rdA0 = s0 + a_row * LDT + a_qc * 16;
    const uint32_t rdH0 = s0 + CLF_T + b_row * LDT + b_qc * 16;
    const uint32_t rdL0 = rdH0 + CLF_T;

    float acc[2][8][4];
#pragma unroll
    for (int mt = 0; mt < 2; mt++)
#pragma unroll
        for (int nt = 0; nt < 8; nt++)
#pragma unroll
            for (int c = 0; c < 4; c++) acc[mt][nt][c] = 0.0f;

    auto issue = [&](int ch, int st) {
        const uint32_t off = st * CLF_STG;
        const int kc = ch * 64;
        cp16(wA + off, gA + kc);
        cp16(wA + off + 64 * LDT, gA + (size_t)64 * HV * 2 + kc);
        cp16(wH + off, gH + kc);
        cp16(wH + off + 64 * LDT, gH + (size_t)64 * HV * 2 + kc);
        cp16(wL + off, gL + kc);
        cp16(wL + off + 64 * LDT, gL + (size_t)64 * HV * 2 + kc);
        CP_COMMIT();
    };
    issue(0, 0);
    issue(1, 1);

    int st = 0, st_wr = 2;
    for (int ch = 0; ch < NCH; ch++) {
        if (ch + 1 < NCH) { CP_WAIT(1); } else { CP_WAIT(0); }
        __syncthreads();
        if (ch + 2 < NCH) {
            issue(ch + 2, st_wr);
            st_wr = (st_wr == 2) ? 0 : st_wr + 1;
        }
        const uint32_t rdA = rdA0 + st * CLF_STG;
        const uint32_t rdH = rdH0 + st * CLF_STG;
        const uint32_t rdL = rdL0 + st * CLF_STG;
#pragma unroll
        for (int ks = 0; ks < 2; ks++) {  // two k16 steps per 64B chunk
            uint32_t af[2][4];
            ldm_x4(af[0], rdA + ks * 32);
            ldm_x4(af[1], rdA + 16 * LDT + ks * 32);
            uint32_t bh[8][2], bl[8][2];
#pragma unroll
            for (int nt2 = 0; nt2 < 4; nt2++) {
                uint32_t t[4];
                ldm_x4(t, rdH + nt2 * 16 * LDT + ks * 32);
                bh[2 * nt2][0] = t[0]; bh[2 * nt2][1] = t[1];
                bh[2 * nt2 + 1][0] = t[2]; bh[2 * nt2 + 1][1] = t[3];
                ldm_x4(t, rdL + nt2 * 16 * LDT + ks * 32);
                bl[2 * nt2][0] = t[0]; bl[2 * nt2][1] = t[1];
                bl[2 * nt2 + 1][0] = t[2]; bl[2 * nt2 + 1][1] = t[3];
            }
#pragma unroll
            for (int mt = 0; mt < 2; mt++)
#pragma unroll
                for (int nt = 0; nt < 8; nt++) {
                    mma_bf16(acc[mt][nt], af[mt], bh[nt][0], bh[nt][1]);
                    mma_bf16(acc[mt][nt], af[mt], bl[nt][0], bl[nt][1]);
                }
        }
        st = (st == 2) ? 0 : st + 1;
    }

    {
        const int g  = lane >> 2;
        const int tg = lane & 3;
        const int rbase = m0 + wm * 32 + g;
        const int cbase = wn * 64 + tg * 2;
#pragma unroll
        for (int mt = 0; mt < 2; mt++) {
            const int r0 = rbase + mt * 16;
            const int r1 = r0 + 8;
#pragma unroll
            for (int nt = 0; nt < 8; nt++) {
                const int c = cbase + nt * 8;
                *(float2*)(C + (size_t)r0 * LV + c) =
                    make_float2(acc[mt][nt][0], acc[mt][nt][1]);
                *(float2*)(C + (size_t)r1 * LV + c) =
                    make_float2(acc[mt][nt][2], acc[mt][nt][3]);
            }
        }
    }
}

// ---------------------------------------------------------------------------
// Launch.  Output layout: [output (B*D) | classification (B*L) | z (B*H)].
// ---------------------------------------------------------------------------
extern "C" void kernel_launch(void* const* d_in, const int* in_sizes, int n_in,
                              void* d_out, int out_size) {
    const float* x     = (const float*)d_in[0];
    const float* w     = (const float*)d_in[1];
    const float* bias0 = (const float*)d_in[2];
    const float* bias3 = (const float*)d_in[3];
    const float* clf   = (const float*)d_in[4];

    float* out        = (float*)d_out;
    float* out_output = out;
    float* out_class  = out + (size_t)BV * DV;
    float* out_z      = out + (size_t)BV * DV + (size_t)BV * LV;

    uint8_t *x8, *w8, *wT8, *z8;
    uint16_t *zbf, *whi, *wlo;
    cudaGetSymbolAddress((void**)&x8, g_x8);
    cudaGetSymbolAddress((void**)&w8, g_w8);
    cudaGetSymbolAddress((void**)&wT8, g_wT8);
    cudaGetSymbolAddress((void**)&z8, g_z8);
    cudaGetSymbolAddress((void**)&zbf, g_zbf);
    cudaGetSymbolAddress((void**)&whi, g_whi);
    cudaGetSymbolAddress((void**)&wlo, g_wlo);

    cudaFuncSetAttribute(fp8_mma_gemm_kernel<DV, true>,
                         cudaFuncAttributeMaxDynamicSharedMemorySize, GEMM_SMEM);
    cudaFuncSetAttribute(fp8_mma_gemm_kernel<HV, false>,
                         cudaFuncAttributeMaxDynamicSharedMemorySize, GEMM_SMEM);
    cudaFuncSetAttribute(clf_mma_kernel,
                         cudaFuncAttributeMaxDynamicSharedMemorySize, CLF_SMEM);

    // 1) conversions
    cvt_fp8_kernel<<<(BV * DV / 4) / 256, 256>>>(x, (uint32_t*)x8, BV * DV / 4);
    cvt_fp8_kernel<<<(HV * DV / 4) / 256, 256>>>(w, (uint32_t*)w8, HV * DV / 4);
    cvt_fp8_transpose_kernel<<<dim3(DV / 256, HV / 32), 256>>>(w, wT8);
    cvt_wsplit_kernel<<<(LV * HV) / 256, 256>>>(clf, whi, wlo, LV * HV);

    // 2) GEMM1: z = (x @ wb^T + bias0 > 1); emits float + e4m3 + bf16 copies
    fp8_mma_gemm_kernel<DV, true>
        <<<dim3(HV / 128, BV / 128), 256, GEMM_SMEM>>>(x8, w8, bias0, out_z, z8,
                                                       zbf, HV);

    // 3) GEMM2: output = (z @ wb + bias3 > 1)
    fp8_mma_gemm_kernel<HV, false>
        <<<dim3(DV / 128, BV / 128), 256, GEMM_SMEM>>>(z8, wT8, bias3, out_output,
                                                       nullptr, nullptr, DV);

    // 4) classification = z @ clf^T  (bf16 split, fp32 accum)
    clf_mma_kernel<<<BV / 128, 256, CLF_SMEM>>>(zbf, whi, wlo, out_class);
}